// round 1
// baseline (speedup 1.0000x reference)
#include <cuda_runtime.h>
#include <cuda_bf16.h>

// BilateralSlice: grid (4,12,8,16,16) f32, guide (4,1,1024,1024) f32
// out (4,12,1024,1024) f32.
// One CTA = (batch b, 8 output rows). Grid[b] (96KB) staged in dynamic SMEM
// with layout [z][(y*16+x)][c] and padded z-plane stride so that the
// guide-dependent z axis maps to disjoint bank groups (conflict-free LDS.128).

#define NB 4
#define NC 12
#define DG 8
#define HG 16
#define WG 16
#define HH 1024
#define WW 1024

constexpr int PLANE_RAW   = HG * WG * NC;          // 3072 floats per z-plane
constexpr int PLANE       = PLANE_RAW + 4;         // pad: stride mod 32 = 4 banks
constexpr int SMEM_FLOATS = DG * PLANE;            // 24608
constexpr int SMEM_BYTES  = SMEM_FLOATS * 4;       // 98432 B
constexpr int THREADS     = 256;
constexpr int ROWS_PER_CTA = 8;
constexpr int ROWGROUPS   = HH / ROWS_PER_CTA;     // 128
constexpr int PIX_PER_CTA = ROWS_PER_CTA * WW;     // 8192
constexpr int ITERS       = PIX_PER_CTA / THREADS; // 32

__global__ void __launch_bounds__(THREADS, 2)
bilateral_slice_kernel(const float* __restrict__ grid,
                       const float* __restrict__ guide,
                       float* __restrict__ out)
{
    extern __shared__ float sg[];

    const int b        = blockIdx.x / ROWGROUPS;
    const int rowgroup = blockIdx.x % ROWGROUPS;
    const int r0       = rowgroup * ROWS_PER_CTA;
    const int tid      = threadIdx.x;

    // ---- Stage grid[b] into SMEM with layout transform ----
    // global: (((c)*DG + z)*HG + y)*WG + x   (contiguous over i)
    // smem:   z*PLANE + (y*WG + x)*NC + c
    {
        const float* gb = grid + (size_t)b * NC * DG * HG * WG;
        #pragma unroll
        for (int i = tid; i < NC * DG * HG * WG; i += THREADS) {
            int c   = i >> 11;          // / 2048
            int rem = i & 2047;
            int z   = rem >> 8;         // / 256
            int yx  = rem & 255;
            sg[z * PLANE + yx * NC + c] = gb[i];
        }
    }
    __syncthreads();

    const float stepx = 15.0f / 1023.0f;   // (WG-1)/(WW-1)
    const float stepy = 15.0f / 1023.0f;   // (HG-1)/(HH-1)

    #pragma unroll 1
    for (int k = 0; k < ITERS; ++k) {
        const int p = k * THREADS + tid;       // 0..8191
        const int y = r0 + (p >> 10);
        const int x = p & 1023;

        // guide -> z position
        float gv  = __ldg(&guide[((size_t)b * HH + y) * WW + x]);
        float iz  = fminf(fmaxf(gv, 0.0f), 1.0f) * (float)(DG - 1);
        float z0f = floorf(iz);
        int   z0  = (int)z0f;
        int   z1  = min(z0 + 1, DG - 1);
        float fz  = iz - z0f;

        // x interpolation
        float ixf = (float)x * stepx;
        float x0f = floorf(ixf);
        int   x0  = (int)x0f;
        int   x1  = min(x0 + 1, WG - 1);
        float fx  = ixf - x0f;

        // y interpolation
        float iyf = (float)y * stepy;
        float y0f = floorf(iyf);
        int   y0  = (int)y0f;
        int   y1  = min(y0 + 1, HG - 1);
        float fy  = iyf - y0f;

        const float wz[2] = {1.0f - fz, fz};
        const float wy[2] = {1.0f - fy, fy};
        const float wx[2] = {1.0f - fx, fx};
        const int   zi[2] = {z0 * PLANE, z1 * PLANE};
        const int   yi[2] = {y0 * WG, y1 * WG};
        const int   xi[2] = {x0, x1};

        float acc[NC];
        #pragma unroll
        for (int c = 0; c < NC; ++c) acc[c] = 0.0f;

        #pragma unroll
        for (int dz = 0; dz < 2; ++dz) {
            #pragma unroll
            for (int dy = 0; dy < 2; ++dy) {
                const float wzy = wz[dz] * wy[dy];
                #pragma unroll
                for (int dx = 0; dx < 2; ++dx) {
                    const float w = wzy * wx[dx];
                    const float4* p4 = reinterpret_cast<const float4*>(
                        &sg[zi[dz] + (yi[dy] + xi[dx]) * NC]);
                    float4 v0 = p4[0];
                    float4 v1 = p4[1];
                    float4 v2 = p4[2];
                    acc[0]  = fmaf(w, v0.x, acc[0]);
                    acc[1]  = fmaf(w, v0.y, acc[1]);
                    acc[2]  = fmaf(w, v0.z, acc[2]);
                    acc[3]  = fmaf(w, v0.w, acc[3]);
                    acc[4]  = fmaf(w, v1.x, acc[4]);
                    acc[5]  = fmaf(w, v1.y, acc[5]);
                    acc[6]  = fmaf(w, v1.z, acc[6]);
                    acc[7]  = fmaf(w, v1.w, acc[7]);
                    acc[8]  = fmaf(w, v2.x, acc[8]);
                    acc[9]  = fmaf(w, v2.y, acc[9]);
                    acc[10] = fmaf(w, v2.z, acc[10]);
                    acc[11] = fmaf(w, v2.w, acc[11]);
                }
            }
        }

        // coalesced per-channel stores (warp = 32 consecutive x)
        size_t obase = ((size_t)b * NC) * (size_t)(HH * WW)
                     + (size_t)y * WW + x;
        #pragma unroll
        for (int c = 0; c < NC; ++c) {
            out[obase + (size_t)c * (HH * WW)] = acc[c];
        }
    }
}

extern "C" void kernel_launch(void* const* d_in, const int* in_sizes, int n_in,
                              void* d_out, int out_size)
{
    // Identify inputs by element count (robust to metadata ordering):
    // grid = 4*12*8*16*16 = 98304, guide = 4*1*1024*1024 = 4194304
    const float* grid  = nullptr;
    const float* guide = nullptr;
    for (int i = 0; i < n_in; ++i) {
        if (in_sizes[i] == NB * NC * DG * HG * WG) grid  = (const float*)d_in[i];
        else if (in_sizes[i] == NB * HH * WW)      guide = (const float*)d_in[i];
    }

    cudaFuncSetAttribute(bilateral_slice_kernel,
                         cudaFuncAttributeMaxDynamicSharedMemorySize, SMEM_BYTES);

    dim3 gridDim(NB * ROWGROUPS);   // 512 CTAs
    bilateral_slice_kernel<<<gridDim, THREADS, SMEM_BYTES>>>(
        grid, guide, (float*)d_out);
}

// round 2
// speedup vs baseline: 1.3032x; 1.3032x over previous
#include <cuda_runtime.h>
#include <cuda_bf16.h>

// BilateralSlice: grid (4,12,8,16,16) f32, guide (4,1,1024,1024) f32,
// out (4,12,1024,1024) f32.
//
// One CTA = one output row (b, y). Since y is fixed per CTA, the grid's
// y-interpolation is folded into a staged slice:
//   S[x][cp][z] = float4{ c0[z], c1[z], c0[z+1], c1[z+1] }   (y-lerped)
// (cp = channel pair, z+1 clamped). 768 float4 = 12 KB.
// Per pixel: 2 x-corners * 6 channel-pairs = 12 LDS.128 give all 4 (x,z)
// corners for 12 channels; 48 FMA of 4 weights.
// z0 varies per lane over 0..7 -> 16B*8 = 128B span -> conflict-free.

#define NB 4
#define NC 12
#define DG 8
#define HG 16
#define WG 16
#define HH 1024
#define WW 1024

__global__ void __launch_bounds__(256, 4)
bilateral_slice_kernel(const float* __restrict__ grid,
                       const float* __restrict__ guide,
                       float* __restrict__ out)
{
    __shared__ float  raw[2][NC * DG * WG];   // [yrow][c*128 + z*16 + x]  12 KB
    __shared__ float4 S[WG * 6 * DG];         // [(x*6+cp)*8 + z]          12 KB

    const int b   = blockIdx.x >> 10;
    const int y   = blockIdx.x & 1023;
    const int tid = threadIdx.x;

    // ---- per-row y interpolation parameters ----
    const float iyf = (float)y * (15.0f / 1023.0f);
    const float y0f = floorf(iyf);
    const int   y0  = (int)y0f;
    const int   y1  = min(y0 + 1, HG - 1);
    const float fy  = iyf - y0f;
    const float wy0 = 1.0f - fy;
    const float wy1 = fy;

    // ---- stage raw grid rows y0, y1 (coalesced 64B chunks, L2-resident) ----
    const float* gb = grid + (size_t)b * (NC * DG * HG * WG);
    #pragma unroll
    for (int i = tid; i < NC * DG * WG; i += 256) {
        int cz = i >> 4;          // c*8 + z
        int x  = i & 15;
        raw[0][i] = gb[cz * (HG * WG) + y0 * WG + x];
        raw[1][i] = gb[cz * (HG * WG) + y1 * WG + x];
    }
    __syncthreads();

    // ---- build y-interpolated, z-paired slice S ----
    #pragma unroll
    for (int e = tid; e < WG * 6 * DG; e += 256) {
        int z  = e & 7;
        int xc = e >> 3;          // x*6 + cp
        int cp = xc % 6;
        int x  = xc / 6;
        int c0 = 2 * cp, c1 = c0 + 1;
        int zb = min(z + 1, DG - 1);
        int i00 = c0 * (DG * WG) + z  * WG + x;
        int i10 = c1 * (DG * WG) + z  * WG + x;
        int i01 = c0 * (DG * WG) + zb * WG + x;
        int i11 = c1 * (DG * WG) + zb * WG + x;
        float4 v;
        v.x = wy0 * raw[0][i00] + wy1 * raw[1][i00];
        v.y = wy0 * raw[0][i10] + wy1 * raw[1][i10];
        v.z = wy0 * raw[0][i01] + wy1 * raw[1][i01];
        v.w = wy0 * raw[0][i11] + wy1 * raw[1][i11];
        S[e] = v;
    }
    __syncthreads();

    // ---- per-pixel x/z trilinear completion ----
    const float* gpix = guide + (size_t)b * (HH * WW) + (size_t)y * WW;
    float*       opix = out + (size_t)b * NC * (size_t)(HH * WW)
                            + (size_t)y * WW;

    #pragma unroll
    for (int k = 0; k < 4; ++k) {
        const int x = tid + k * 256;

        float gv  = __ldg(&gpix[x]);
        float iz  = fminf(fmaxf(gv, 0.0f), 1.0f) * (float)(DG - 1);
        float z0f = floorf(iz);
        int   z0  = (int)z0f;
        float fz  = iz - z0f;

        float ixf = (float)x * (15.0f / 1023.0f);
        float x0f = floorf(ixf);
        int   x0  = (int)x0f;
        int   x1  = min(x0 + 1, WG - 1);
        float fx  = ixf - x0f;

        const float w00 = (1.0f - fx) * (1.0f - fz);
        const float w01 = (1.0f - fx) * fz;
        const float w10 = fx * (1.0f - fz);
        const float w11 = fx * fz;

        const int ia = x0 * 48 + z0;   // (x0*6 + cp)*8 + z0, cp stride 8
        const int ib = x1 * 48 + z0;

        float acc[NC];
        #pragma unroll
        for (int cp = 0; cp < 6; ++cp) {
            float4 A = S[ia + cp * 8];
            float4 B = S[ib + cp * 8];
            acc[2*cp]     = fmaf(w00, A.x, fmaf(w01, A.z,
                            fmaf(w10, B.x, w11 * B.z)));
            acc[2*cp + 1] = fmaf(w00, A.y, fmaf(w01, A.w,
                            fmaf(w10, B.y, w11 * B.w)));
        }

        #pragma unroll
        for (int c = 0; c < NC; ++c) {
            opix[x + (size_t)c * (HH * WW)] = acc[c];
        }
    }
}

extern "C" void kernel_launch(void* const* d_in, const int* in_sizes, int n_in,
                              void* d_out, int out_size)
{
    const float* grid  = nullptr;
    const float* guide = nullptr;
    for (int i = 0; i < n_in; ++i) {
        if (in_sizes[i] == NB * NC * DG * HG * WG) grid  = (const float*)d_in[i];
        else if (in_sizes[i] == NB * HH * WW)      guide = (const float*)d_in[i];
    }

    dim3 gridDim(NB * HH);   // 4096 CTAs: one per (batch, row)
    bilateral_slice_kernel<<<gridDim, 256>>>(grid, guide, (float*)d_out);
}

// round 3
// speedup vs baseline: 2.0006x; 1.5351x over previous
#include <cuda_runtime.h>
#include <cuda_fp16.h>

// BilateralSlice: grid (4,12,8,16,16) f32, guide (4,1,1024,1024) f32,
// out (4,12,1024,1024) f32.
//
// One CTA = one output row (b, y). The y-interpolation is folded into a staged
// slice stored as fp16 z-pairs:
//   S[x][z][c] = half2{ v_c(z), v_c(z+1) }   (y-lerped in fp32, z+1 clamped)
// 16 x * 8 z * 12 c half2 = 6.4 KB (x-stride padded to 100 words).
// Per pixel: 2 x-corners * 3 LDS.128 fetch all 12 channels * both z levels
// (96 B/px, half of the fp32 version). Interp math is fp32 after conversion.

#define NB 4
#define NC 12
#define DG 8
#define HG 16
#define WG 16
#define HH 1024
#define WW 1024

constexpr int XSTRIDE = 100;           // words per x (12*8=96 + 4 pad)
constexpr int THREADS = 512;

__global__ void __launch_bounds__(THREADS, 2)
bilateral_slice_kernel(const float* __restrict__ grid,
                       const float* __restrict__ guide,
                       float* __restrict__ out)
{
    __shared__ unsigned int S[WG * XSTRIDE];   // half2 entries, 6.4 KB

    const int b   = blockIdx.x >> 10;
    const int y   = blockIdx.x & 1023;
    const int tid = threadIdx.x;

    // ---- per-row y interpolation parameters ----
    const float iyf = (float)y * (15.0f / 1023.0f);
    const float y0f = floorf(iyf);
    const int   y0  = (int)y0f;
    const int   y1  = min(y0 + 1, HG - 1);
    const float fy  = iyf - y0f;
    const float wy0 = 1.0f - fy;

    // ---- stage y-lerped, z-paired fp16 slice (grid is L2-resident) ----
    const float* gb = grid + (size_t)b * (NC * DG * HG * WG);
    #pragma unroll
    for (int i = tid; i < WG * DG * NC; i += THREADS) {
        int x  = i & 15;
        int zc = i >> 4;            // z*12 + c
        int z  = zc / 12;
        int c  = zc - z * 12;
        int zb = min(z + 1, DG - 1);
        const float* pz  = gb + (c * DG + z)  * (HG * WG);
        const float* pzb = gb + (c * DG + zb) * (HG * WG);
        float va = wy0 * pz[y0 * WG + x]  + fy * pz[y1 * WG + x];
        float vb = wy0 * pzb[y0 * WG + x] + fy * pzb[y1 * WG + x];
        __half2 h = __floats2half2_rn(va, vb);   // {v(z), v(z+1)}
        S[x * XSTRIDE + z * 12 + c] = *reinterpret_cast<unsigned int*>(&h);
    }
    __syncthreads();

    // ---- per-pixel x/z trilinear completion, 2 px per thread ----
    const int xb = tid * 2;
    const float2 g2 = *reinterpret_cast<const float2*>(
        guide + (size_t)b * (HH * WW) + (size_t)y * WW + xb);
    float*       opix = out + (size_t)b * NC * (size_t)(HH * WW)
                            + (size_t)y * WW + xb;

    float r0[NC], r1[NC];

    #pragma unroll
    for (int j = 0; j < 2; ++j) {
        const int   x  = xb + j;
        const float gv = j ? g2.y : g2.x;

        float iz  = fminf(fmaxf(gv, 0.0f), 1.0f) * (float)(DG - 1);
        float z0f = floorf(iz);
        int   z0  = (int)z0f;
        float fz  = iz - z0f;

        float ixf = (float)x * (15.0f / 1023.0f);
        float x0f = floorf(ixf);
        int   x0  = (int)x0f;
        int   x1  = min(x0 + 1, WG - 1);
        float fx  = ixf - x0f;

        const float w00 = (1.0f - fx) * (1.0f - fz);   // x0, z0
        const float w01 = (1.0f - fx) * fz;            // x0, z1
        const float w10 = fx * (1.0f - fz);            // x1, z0
        const float w11 = fx * fz;                     // x1, z1

        const uint4* pa = reinterpret_cast<const uint4*>(
            &S[x0 * XSTRIDE + z0 * 12]);
        const uint4* pb = reinterpret_cast<const uint4*>(
            &S[x1 * XSTRIDE + z0 * 12]);
        uint4 A0 = pa[0], A1 = pa[1], A2 = pa[2];
        uint4 B0 = pb[0], B1 = pb[1], B2 = pb[2];

        float* res = j ? r1 : r0;
        const unsigned int Aw[12] = {A0.x, A0.y, A0.z, A0.w,
                                     A1.x, A1.y, A1.z, A1.w,
                                     A2.x, A2.y, A2.z, A2.w};
        const unsigned int Bw[12] = {B0.x, B0.y, B0.z, B0.w,
                                     B1.x, B1.y, B1.z, B1.w,
                                     B2.x, B2.y, B2.z, B2.w};
        #pragma unroll
        for (int c = 0; c < NC; ++c) {
            float2 va = __half22float2(
                *reinterpret_cast<const __half2*>(&Aw[c]));
            float2 vb = __half22float2(
                *reinterpret_cast<const __half2*>(&Bw[c]));
            res[c] = fmaf(w00, va.x, fmaf(w01, va.y,
                     fmaf(w10, vb.x, w11 * vb.y)));
        }
    }

    #pragma unroll
    for (int c = 0; c < NC; ++c) {
        float2 o = make_float2(r0[c], r1[c]);
        *reinterpret_cast<float2*>(opix + (size_t)c * (HH * WW)) = o;
    }
}

extern "C" void kernel_launch(void* const* d_in, const int* in_sizes, int n_in,
                              void* d_out, int out_size)
{
    const float* grid  = nullptr;
    const float* guide = nullptr;
    for (int i = 0; i < n_in; ++i) {
        if (in_sizes[i] == NB * NC * DG * HG * WG) grid  = (const float*)d_in[i];
        else if (in_sizes[i] == NB * HH * WW)      guide = (const float*)d_in[i];
    }

    dim3 gridDim(NB * HH);   // 4096 CTAs: one per (batch, row)
    bilateral_slice_kernel<<<gridDim, THREADS>>>(grid, guide, (float*)d_out);
}